// round 11
// baseline (speedup 1.0000x reference)
#include <cuda_runtime.h>
#include <math.h>
#include <stdint.h>

#define TT 4096
#define DD 2048
#define FFDIM 8192
#define EE 8
#define MT 16

constexpr float RANGE_X  = 6.5f;
constexpr float RANGE_W1 = 6.5f * 0.022097086912079608f;   // 6.5/sqrt(2048)
constexpr float RANGE_W2 = 6.5f * 0.011048543456039804f;   // 6.5/sqrt(8192)
constexpr float RANGE_H  = 6.5f;
constexpr float INV_X  = 32768.0f / RANGE_X;
constexpr float INV_W1 = 32768.0f / RANGE_W1;
constexpr float INV_W2 = 32768.0f / RANGE_W2;
constexpr float INV_H  = 32768.0f / RANGE_H;
constexpr float S1 = (RANGE_X / 32768.0f) * (RANGE_W1 / 32768.0f);
constexpr float S2 = (RANGE_H / 32768.0f) * (RANGE_W2 / 32768.0f);

// ---------------- device scratch ----------------
__device__ int8_t g_xq[2][(size_t)TT * DD];             // hi/lo planes [T][D]
__device__ int8_t g_Hq[2][(size_t)TT * FFDIM];          // sorted rows  [T][F]
__device__ int8_t g_W1q[2][(size_t)EE * FFDIM * DD];    // [E][N=F][K=D]
__device__ int8_t g_W2q[2][(size_t)EE * DD * FFDIM];    // [E][N=D][K=F]
__device__ int   g_idx[TT];
__device__ float g_w[TT];
__device__ int   g_counts[EE];
__device__ int   g_offsets[EE];
__device__ int   g_rank[TT];
__device__ int   g_perm[TT];

// ---------------- helpers ----------------
__device__ __forceinline__ uint32_t smem_u32(const void* p) {
    uint32_t a;
    asm("{ .reg .u64 t; cvta.to.shared.u64 t, %1; cvt.u32.u64 %0, t; }" : "=r"(a) : "l"(p));
    return a;
}
__device__ __forceinline__ uint32_t sw128(uint32_t b) { return b ^ ((b >> 3) & 0x70); }

// radix-256 split: v ~= s*(hi*256+lo)
__device__ __forceinline__ void quant8(float v, float inv_s, int& hi, int& lo) {
    float q  = v * inv_s;
    float hf = rintf(q * 0.00390625f);
    hi = max(-128, min(127, (int)hf));
    lo = max(-128, min(127, __float2int_rn(q - hf * 256.0f)));
}
__device__ __forceinline__ uint32_t pack4(int a0, int a1, int a2, int a3) {
    return (uint32_t)(a0 & 255) | ((uint32_t)(a1 & 255) << 8) |
           ((uint32_t)(a2 & 255) << 16) | ((uint32_t)(a3 & 255) << 24);
}
__device__ __forceinline__ void ldm4(uint32_t* r, uint32_t addr) {
    asm volatile("ldmatrix.sync.aligned.m8n8.x4.shared.b16 {%0,%1,%2,%3}, [%4];"
        : "=r"(r[0]), "=r"(r[1]), "=r"(r[2]), "=r"(r[3]) : "r"(addr));
}
__device__ __forceinline__ void mma_s8(int* d, const uint32_t* a, uint32_t b0, uint32_t b1) {
    asm volatile("mma.sync.aligned.m16n8k32.row.col.s32.s8.s8.s32 "
        "{%0,%1,%2,%3}, {%4,%5,%6,%7}, {%8,%9}, {%0,%1,%2,%3};"
        : "+r"(d[0]), "+r"(d[1]), "+r"(d[2]), "+r"(d[3])
        : "r"(a[0]), "r"(a[1]), "r"(a[2]), "r"(a[3]), "r"(b0), "r"(b1));
}
#define CP16(dst, src) asm volatile("cp.async.cg.shared.global [%0], [%1], 16;" :: "r"(dst), "l"(src))
#define CP_COMMIT()    asm volatile("cp.async.commit_group;" ::: "memory")
#define CP_WAIT0()     asm volatile("cp.async.wait_group 0;" ::: "memory")

__device__ __forceinline__ float gelu_exact(float v) {
    return 0.5f * v * (1.0f + erff(v * 0.70710678118654752440f));
}

// ---------------- pre-pass quantization ----------------
__global__ void quant_x_kernel(const float* __restrict__ x) {
    size_t i4 = (size_t)blockIdx.x * 256 + threadIdx.x;
    float4 v = ((const float4*)x)[i4];
    int h0, l0, h1, l1, h2, l2, h3, l3;
    quant8(v.x, INV_X, h0, l0); quant8(v.y, INV_X, h1, l1);
    quant8(v.z, INV_X, h2, l2); quant8(v.w, INV_X, h3, l3);
    ((uint32_t*)g_xq[0])[i4] = pack4(h0, h1, h2, h3);
    ((uint32_t*)g_xq[1])[i4] = pack4(l0, l1, l2, l3);
}

// W [E][K][N] fp32 -> planes [E][N][K] int8 (transpose + quantize)
template<int L>
__global__ void quant_w_kernel(const float* __restrict__ W) {
    constexpr int KK = (L == 0) ? DD : FFDIM;
    constexpr int NN = (L == 0) ? FFDIM : DD;
    const float inv = (L == 0) ? INV_W1 : INV_W2;
    __shared__ float t[32][33];
    const int e = blockIdx.z, n0 = blockIdx.x * 32, k0 = blockIdx.y * 32;
    const int nn = threadIdx.x & 31, kr = threadIdx.x >> 5;
    const float* src = W + ((size_t)e * KK + k0) * NN + n0;
    #pragma unroll
    for (int i = 0; i < 4; i++)
        t[kr + 8 * i][nn] = src[(size_t)(kr + 8 * i) * NN + nn];
    __syncthreads();
    const int n = threadIdx.x >> 3, kg = (threadIdx.x & 7) * 4;
    int h[4], l[4];
    #pragma unroll
    for (int i = 0; i < 4; i++) quant8(t[kg + i][n], inv, h[i], l[i]);
    size_t o = ((size_t)e * NN + n0 + n) * KK + k0 + kg;
    int8_t* ph = (L == 0) ? g_W1q[0] : g_W2q[0];
    int8_t* pl = (L == 0) ? g_W1q[1] : g_W2q[1];
    *(uint32_t*)(ph + o) = pack4(h[0], h[1], h[2], h[3]);
    *(uint32_t*)(pl + o) = pack4(l[0], l[1], l[2], l[3]);
}

// ---------------- router pipeline ----------------
__global__ void zero_counts_kernel() { if (threadIdx.x < EE) g_counts[threadIdx.x] = 0; }

__global__ void router_kernel(const float* __restrict__ x, const float* __restrict__ Wr) {
    const int t = blockIdx.x;
    const int warp = threadIdx.x >> 5, lane = threadIdx.x & 31;
    const float* xr = x + (size_t)t * DD;
    const float* wr = Wr + (size_t)warp * DD;
    float acc = 0.0f;
    for (int d = lane * 4; d < DD; d += 128) {
        float4 xv = *(const float4*)(xr + d);
        float4 wv = *(const float4*)(wr + d);
        acc += xv.x * wv.x + xv.y * wv.y + xv.z * wv.z + xv.w * wv.w;
    }
    #pragma unroll
    for (int o = 16; o; o >>= 1) acc += __shfl_xor_sync(0xFFFFFFFFu, acc, o);
    __shared__ float slog[EE];
    if (lane == 0) slog[warp] = acc;
    __syncthreads();
    if (threadIdx.x == 0) {
        float mx = slog[0]; int mi = 0;
        #pragma unroll
        for (int e = 1; e < EE; e++) if (slog[e] > mx) { mx = slog[e]; mi = e; }
        float s = 0.0f;
        #pragma unroll
        for (int e = 0; e < EE; e++) s += expf(slog[e] - mx);
        g_idx[t] = mi; g_w[t] = 1.0f / s;
        g_rank[t] = atomicAdd(&g_counts[mi], 1);
    }
}

__global__ void scan_kernel() {
    int s = 0;
    #pragma unroll
    for (int e = 0; e < EE; e++) { g_offsets[e] = s; s += g_counts[e]; }
}

__global__ void scatter_kernel() {
    int t = blockIdx.x * blockDim.x + threadIdx.x;
    if (t < TT) g_perm[g_offsets[g_idx[t]] + g_rank[t]] = t;
}

// ---------------- int8 grouped GEMM, m16n8k32, 4-pass exact 16-bit ----------------
constexpr int BM = 128, BN = 32, BKB = 128;      // k-bytes per stage
constexpr int A_PL = BM * BKB;                   // 16 KB per plane
constexpr int B_PL = BN * BKB;                   // 4 KB per plane
constexpr int BUF  = 2 * A_PL + 2 * B_PL;        // 40 KB
constexpr int SMEMT = 2 * BUF;                   // 80 KB

template<int MODE>
__global__ __launch_bounds__(128, 2) void moe_gemm_i8(float* __restrict__ Cg)
{
    constexpr int K  = (MODE == 0) ? DD : FFDIM;
    constexpr int NN = (MODE == 0) ? FFDIM : DD;
    constexpr int KT = K / BKB;

    const int e   = blockIdx.z;
    const int cnt = g_counts[e];
    const int m0  = blockIdx.x * BM;
    if (m0 >= cnt) return;
    const int off = g_offsets[e];
    const int n0  = blockIdx.y * BN;

    extern __shared__ __align__(1024) char smem[];
    const uint32_t su = smem_u32(smem);
    const int tid = threadIdx.x, wid = tid >> 5, lane = tid & 31;

    const int8_t* Ah = (MODE == 0) ? g_xq[0] : g_Hq[0];
    const int8_t* Al = (MODE == 0) ? g_xq[1] : g_Hq[1];
    const int8_t* Bh = (MODE == 0) ? g_W1q[0] : g_W2q[0];
    const int8_t* Bl = (MODE == 0) ? g_W1q[1] : g_W2q[1];

    // A staging: thread owns 8 rows m=(tid>>3)+16j at fixed 16B chunk kc=tid&7
    const int kc = tid & 7;
    uint32_t aRowB[8], sA[8];
    #pragma unroll
    for (int j = 0; j < 8; j++) {
        int m = (tid >> 3) + 16 * j;
        int r = m0 + m;
        bool v = r < cnt;
        if (MODE == 0) {
            int tok = v ? g_perm[off + r] : g_perm[off];
            aRowB[j] = (uint32_t)tok * DD;
        } else {
            aRowB[j] = (uint32_t)(off + (v ? r : 0)) * FFDIM;
        }
        sA[j] = sw128((uint32_t)(m * 128 + kc * 16));
    }
    // B staging: rows rb=(tid>>3), rb+16
    size_t bRowB[2]; uint32_t sB[2];
    #pragma unroll
    for (int j = 0; j < 2; j++) {
        int rb = (tid >> 3) + 16 * j;
        bRowB[j] = ((size_t)e * NN + n0 + rb) * K;
        sB[j] = sw128((uint32_t)(rb * 128 + kc * 16));
    }

    // ldmatrix addresses
    uint32_t aB[2], bB[2];
    #pragma unroll
    for (int c = 0; c < 2; c++)
        aB[c] = (uint32_t)((wid * 32 + c * 16 + (lane & 15)) * 128 + (lane >> 4) * 16);
    #pragma unroll
    for (int j = 0; j < 2; j++)
        bB[j] = (uint32_t)((j * 16 + (lane & 15)) * 128 + (lane >> 4) * 16);

    int accH[2][4][4], accM[2][4][4], accL[2][4][4];
    #pragma unroll
    for (int c = 0; c < 2; c++)
        #pragma unroll
        for (int j = 0; j < 4; j++)
            #pragma unroll
            for (int q = 0; q < 4; q++) { accH[c][j][q] = 0; accM[c][j][q] = 0; accL[c][j][q] = 0; }

    auto stage = [&](int kt, int b) {
        const uint32_t d = su + b * BUF;
        const uint32_t ko = (uint32_t)(kt * BKB) + kc * 16;
        #pragma unroll
        for (int j = 0; j < 8; j++) CP16(d + sA[j], Ah + aRowB[j] + ko);
        #pragma unroll
        for (int j = 0; j < 8; j++) CP16(d + A_PL + sA[j], Al + aRowB[j] + ko);
        #pragma unroll
        for (int j = 0; j < 2; j++) CP16(d + 2 * A_PL + sB[j], Bh + bRowB[j] + ko);
        #pragma unroll
        for (int j = 0; j < 2; j++) CP16(d + 2 * A_PL + B_PL + sB[j], Bl + bRowB[j] + ko);
    };

    stage(0, 0); CP_COMMIT();

    for (int kt = 0; kt < KT; kt++) {
        const int b = kt & 1;
        CP_WAIT0();
        __syncthreads();
        if (kt + 1 < KT) { stage(kt + 1, b ^ 1); CP_COMMIT(); }

        const uint32_t dA = su + b * BUF, dAl = dA + A_PL;
        const uint32_t dB = dA + 2 * A_PL, dBl = dB + B_PL;
        #pragma unroll
        for (int ks = 0; ks < 4; ks++) {
            uint32_t ah[2][4], al[2][4], bh[2][4], bl[2][4];
            #pragma unroll
            for (int c = 0; c < 2; c++) {
                uint32_t o = sw128(aB[c] + ks * 32);
                ldm4(ah[c], dA + o); ldm4(al[c], dAl + o);
            }
            #pragma unroll
            for (int j = 0; j < 2; j++) {
                uint32_t o = sw128(bB[j] + ks * 32);
                ldm4(bh[j], dB + o); ldm4(bl[j], dBl + o);
            }
            #pragma unroll
            for (int j = 0; j < 2; j++)
                #pragma unroll
                for (int c = 0; c < 2; c++) {
                    mma_s8(accH[c][2 * j],     ah[c], bh[j][0], bh[j][2]);
                    mma_s8(accH[c][2 * j + 1], ah[c], bh[j][1], bh[j][3]);
                }
            #pragma unroll
            for (int j = 0; j < 2; j++)
                #pragma unroll
                for (int c = 0; c < 2; c++) {
                    mma_s8(accM[c][2 * j],     ah[c], bl[j][0], bl[j][2]);
                    mma_s8(accM[c][2 * j + 1], ah[c], bl[j][1], bl[j][3]);
                    mma_s8(accM[c][2 * j],     al[c], bh[j][0], bh[j][2]);
                    mma_s8(accM[c][2 * j + 1], al[c], bh[j][1], bh[j][3]);
                }
            #pragma unroll
            for (int j = 0; j < 2; j++)
                #pragma unroll
                for (int c = 0; c < 2; c++) {
                    mma_s8(accL[c][2 * j],     al[c], bl[j][0], bl[j][2]);
                    mma_s8(accL[c][2 * j + 1], al[c], bl[j][1], bl[j][3]);
                }
        }
        __syncthreads();
    }

    // ---------------- epilogue ----------------
    const int mw = m0 + wid * 32;
    #pragma unroll
    for (int c = 0; c < 2; c++) {
        #pragma unroll
        for (int half = 0; half < 2; half++) {
            const int r = mw + c * 16 + (lane >> 2) + half * 8;
            if (r >= cnt) continue;
            const int q = half * 2;
            if (MODE == 0) {
                size_t ro = (size_t)(off + r) * FFDIM + n0;
                #pragma unroll
                for (int j = 0; j < 4; j++) {
                    float v0 = S1 * (65536.0f * (float)accH[c][j][q]     + 256.0f * (float)accM[c][j][q]     + (float)accL[c][j][q]);
                    float v1 = S1 * (65536.0f * (float)accH[c][j][q + 1] + 256.0f * (float)accM[c][j][q + 1] + (float)accL[c][j][q + 1]);
                    v0 = gelu_exact(v0); v1 = gelu_exact(v1);
                    int h0, l0, h1, l1;
                    quant8(v0, INV_H, h0, l0); quant8(v1, INV_H, h1, l1);
                    int n = j * 8 + (lane & 3) * 2;
                    *(uint16_t*)&g_Hq[0][ro + n] = (uint16_t)((h0 & 255) | ((h1 & 255) << 8));
                    *(uint16_t*)&g_Hq[1][ro + n] = (uint16_t)((l0 & 255) | ((l1 & 255) << 8));
                }
            } else {
                const int tok = g_perm[off + r];
                const float s = g_w[tok] * S2;
                float* cp = Cg + (size_t)tok * DD + n0;
                #pragma unroll
                for (int j = 0; j < 4; j++) {
                    float v0 = s * (65536.0f * (float)accH[c][j][q]     + 256.0f * (float)accM[c][j][q]     + (float)accL[c][j][q]);
                    float v1 = s * (65536.0f * (float)accH[c][j][q + 1] + 256.0f * (float)accM[c][j][q + 1] + (float)accL[c][j][q + 1]);
                    *(float2*)(cp + j * 8 + (lane & 3) * 2) = make_float2(v0, v1);
                }
            }
        }
    }
}

// ---------------- launch ----------------
extern "C" void kernel_launch(void* const* d_in, const int* in_sizes, int n_in,
                              void* d_out, int out_size) {
    const float* x  = (const float*)d_in[0];
    const float* Wr = (const float*)d_in[1];
    const float* W1 = (const float*)d_in[2];
    const float* W2 = (const float*)d_in[3];
    float* out = (float*)d_out;

    cudaFuncSetAttribute(moe_gemm_i8<0>, cudaFuncAttributeMaxDynamicSharedMemorySize, SMEMT);
    cudaFuncSetAttribute(moe_gemm_i8<1>, cudaFuncAttributeMaxDynamicSharedMemorySize, SMEMT);

    quant_x_kernel<<<TT * DD / 1024, 256>>>(x);
    quant_w_kernel<0><<<dim3(FFDIM / 32, DD / 32, EE), 256>>>(W1);
    quant_w_kernel<1><<<dim3(DD / 32, FFDIM / 32, EE), 256>>>(W2);

    zero_counts_kernel<<<1, 32>>>();
    router_kernel<<<TT, 256>>>(x, Wr);
    scan_kernel<<<1, 1>>>();
    scatter_kernel<<<TT / 256, 256>>>();

    dim3 g1(MT, FFDIM / BN, EE);
    moe_gemm_i8<0><<<g1, 128, SMEMT>>>(nullptr);

    dim3 g2(MT, DD / BN, EE);
    moe_gemm_i8<1><<<g2, 128, SMEMT>>>(out);
}

// round 12
// speedup vs baseline: 5.1548x; 5.1548x over previous
#include <cuda_runtime.h>
#include <math.h>
#include <stdint.h>

#define TT 4096
#define DD 2048
#define FFDIM 8192
#define EE 8
#define MTILES 16   // covers up to 2048 tokens/expert (mean 512)

// ---------------- device scratch ----------------
__device__ float g_H[(size_t)TT * FFDIM];
__device__ int   g_idx[TT];
__device__ float g_w[TT];
__device__ int   g_counts[EE];
__device__ int   g_offsets[EE];
__device__ int   g_rank[TT];
__device__ int   g_perm[TT];

// ---------------- helpers ----------------
__device__ __forceinline__ uint32_t smem_u32(const void* p) {
    uint32_t a;
    asm("{ .reg .u64 t; cvta.to.shared.u64 t, %1; cvt.u32.u64 %0, t; }" : "=r"(a) : "l"(p));
    return a;
}
__device__ __forceinline__ uint32_t sw128(uint32_t b) { return b ^ ((b >> 3) & 0x70); }

// split fp32 pair -> f16x2 hi + f16x2 lo (f0 low half, f1 high half)
__device__ __forceinline__ void split2h(float f0, float f1, uint32_t& hi, uint32_t& lo) {
    uint32_t h;
    asm("cvt.rn.f16x2.f32 %0, %1, %2;" : "=r"(h) : "f"(f1), "f"(f0));
    float h0, h1;
    asm("{ .reg .f16 a, b; mov.b32 {a, b}, %2; cvt.f32.f16 %0, a; cvt.f32.f16 %1, b; }"
        : "=f"(h0), "=f"(h1) : "r"(h));
    float l0 = f0 - h0, l1 = f1 - h1;
    asm("cvt.rn.f16x2.f32 %0, %1, %2;" : "=r"(lo) : "f"(l1), "f"(l0));
    hi = h;
}
__device__ __forceinline__ uint32_t cvt2h(float f0, float f1) {
    uint32_t h;
    asm("cvt.rn.f16x2.f32 %0, %1, %2;" : "=r"(h) : "f"(f1), "f"(f0));
    return h;
}

__device__ __forceinline__ void ldm4(uint32_t* r, uint32_t addr) {
    asm volatile("ldmatrix.sync.aligned.m8n8.x4.shared.b16 {%0,%1,%2,%3}, [%4];"
        : "=r"(r[0]), "=r"(r[1]), "=r"(r[2]), "=r"(r[3]) : "r"(addr));
}

__device__ __forceinline__ void mma_f16(float* d, const uint32_t* a, uint32_t b0, uint32_t b1) {
    asm volatile("mma.sync.aligned.m16n8k16.row.col.f32.f16.f16.f32 "
        "{%0,%1,%2,%3}, {%4,%5,%6,%7}, {%8,%9}, {%0,%1,%2,%3};"
        : "+f"(d[0]), "+f"(d[1]), "+f"(d[2]), "+f"(d[3])
        : "r"(a[0]), "r"(a[1]), "r"(a[2]), "r"(a[3]), "r"(b0), "r"(b1));
}

__device__ __forceinline__ float gelu_exact(float v) {
    return 0.5f * v * (1.0f + erff(v * 0.70710678118654752440f));
}

// ---------------- router pipeline ----------------
__global__ void zero_counts_kernel() { if (threadIdx.x < EE) g_counts[threadIdx.x] = 0; }

__global__ void router_kernel(const float* __restrict__ x, const float* __restrict__ Wr) {
    const int t = blockIdx.x;
    const int warp = threadIdx.x >> 5, lane = threadIdx.x & 31;
    const float* xr = x + (size_t)t * DD;
    const float* wr = Wr + (size_t)warp * DD;
    float acc = 0.0f;
    for (int d = lane * 4; d < DD; d += 128) {
        float4 xv = *(const float4*)(xr + d);
        float4 wv = *(const float4*)(wr + d);
        acc += xv.x * wv.x + xv.y * wv.y + xv.z * wv.z + xv.w * wv.w;
    }
    #pragma unroll
    for (int o = 16; o; o >>= 1) acc += __shfl_xor_sync(0xFFFFFFFFu, acc, o);
    __shared__ float slog[EE];
    if (lane == 0) slog[warp] = acc;
    __syncthreads();
    if (threadIdx.x == 0) {
        float mx = slog[0]; int mi = 0;
        #pragma unroll
        for (int e = 1; e < EE; e++) if (slog[e] > mx) { mx = slog[e]; mi = e; }
        float s = 0.0f;
        #pragma unroll
        for (int e = 0; e < EE; e++) s += expf(slog[e] - mx);
        g_idx[t] = mi;
        g_w[t] = 1.0f / s;
        g_rank[t] = atomicAdd(&g_counts[mi], 1);
    }
}

__global__ void scan_kernel() {
    int s = 0;
    #pragma unroll
    for (int e = 0; e < EE; e++) { g_offsets[e] = s; s += g_counts[e]; }
}

__global__ void scatter_kernel() {
    int t = blockIdx.x * blockDim.x + threadIdx.x;
    if (t < TT) g_perm[g_offsets[g_idx[t]] + g_rank[t]] = t;
}

// ---------------- mma.sync grouped GEMM (fp16 split) ----------------
// MODE 0 (2-pass): H = gelu( x @ W1 )   A=x split hi/lo, B=W1 single fp16
// MODE 1 (3-pass): out = ( H @ W2 ) * w  A=H split, B=W2 split, drop lo*lo
constexpr int BM = 128, BN = 64, BKS = 64;
constexpr int A_TILE = BM * BKS * 2;             // 16 KB per plane
constexpr int B_TILE = BN * BKS * 2;             // 8 KB per plane

template<int MODE>
__global__ __launch_bounds__(128, 2) void moe_gemm_mma(
    const float* __restrict__ Ag, const float* __restrict__ Bg, float* __restrict__ Cg)
{
    constexpr int K  = (MODE == 0) ? DD : FFDIM;
    constexpr int NN = (MODE == 0) ? FFDIM : DD;
    constexpr int KT = K / BKS;
    constexpr int NBP = (MODE == 0) ? 1 : 2;               // B planes
    constexpr int BUF = 2 * A_TILE + NBP * B_TILE;         // 40 KB / 48 KB

    const int e   = blockIdx.z;
    const int cnt = g_counts[e];
    const int m0  = blockIdx.x * BM;             // m fastest -> B tile L2 reuse
    if (m0 >= cnt) return;
    const int off = g_offsets[e];
    const int n0  = blockIdx.y * BN;

    extern __shared__ __align__(1024) char smem[];
    const uint32_t su = smem_u32(smem);
    const int tid = threadIdx.x, wid = tid >> 5, lane = tid & 31;

    // ---- staging geometry ----
    const char* aBase = (MODE == 0) ? (const char*)Ag : (const char*)g_H;
    uint32_t aOff[16], sAoff[16];
    {
        const int mB = tid >> 4, k4 = tid & 15;
        #pragma unroll
        for (int i = 0; i < 16; i++) {
            int m = mB + 8 * i;
            int r = m0 + m;
            bool v = r < cnt;
            uint32_t rowBytes;
            if (MODE == 0) {
                int tok = v ? g_perm[off + r] : g_perm[off];
                rowBytes = (uint32_t)tok * (DD * 4u);
            } else {
                rowBytes = (uint32_t)(off + (v ? r : 0)) * (FFDIM * 4u);
            }
            aOff[i]  = rowBytes + k4 * 16u;
            sAoff[i] = sw128((uint32_t)(m * 128 + k4 * 8));
        }
    }
    const int rB = tid & 63;
    const float* bCol = Bg + (size_t)e * ((size_t)K * NN) + (size_t)(n0 + rB);
    int kkB[8]; uint32_t sBoff[8];
    {
        const int gB = tid >> 6, stag = (rB >> 3) & 3;
        #pragma unroll
        for (int i = 0; i < 8; i++) {
            int g = ((gB + 2 * i) + stag) & 15;
            kkB[i]   = g * 4;
            sBoff[i] = sw128((uint32_t)(rB * 128 + g * 8));
        }
    }

    // ---- ldmatrix geometry ----
    uint32_t aB[2], bB[4];
    #pragma unroll
    for (int c = 0; c < 2; c++) {
        int row = wid * 32 + c * 16 + (lane & 15);
        aB[c] = (uint32_t)(row * 128 + (lane >> 4) * 16);
    }
    #pragma unroll
    for (int j = 0; j < 4; j++) {
        int row = j * 16 + (lane & 15);
        bB[j] = (uint32_t)(row * 128 + (lane >> 4) * 16);
    }

    float acc[2][8][4];
    #pragma unroll
    for (int c = 0; c < 2; c++)
        #pragma unroll
        for (int j = 0; j < 8; j++)
            #pragma unroll
            for (int q = 0; q < 4; q++) acc[c][j][q] = 0.0f;

    float4 pb[8];
    auto preloadB = [&](int kt) {
        const int k0 = kt * BKS;
        #pragma unroll
        for (int i = 0; i < 8; i++) {
            const float* p = bCol + (size_t)(k0 + kkB[i]) * NN;
            pb[i] = make_float4(p[0], p[(size_t)NN], p[(size_t)2 * NN], p[(size_t)3 * NN]);
        }
    };

    auto stageA = [&](int kt, int b) {
        char* Ahi = smem + b * BUF;
        char* Alo = Ahi + A_TILE;
        const uint32_t kByte = (uint32_t)(kt * BKS * 4);
        #pragma unroll
        for (int i = 0; i < 16; i++) {
            float4 v = *(const float4*)(aBase + aOff[i] + kByte);
            uint32_t h0, l0, h1, l1;
            split2h(v.x, v.y, h0, l0);
            split2h(v.z, v.w, h1, l1);
            *(uint2*)(Ahi + sAoff[i]) = make_uint2(h0, h1);
            *(uint2*)(Alo + sAoff[i]) = make_uint2(l0, l1);
        }
    };
    auto storeB = [&](int b) {
        char* Bhi = smem + b * BUF + 2 * A_TILE;
        if (MODE == 0) {
            #pragma unroll
            for (int i = 0; i < 8; i++)
                *(uint2*)(Bhi + sBoff[i]) = make_uint2(cvt2h(pb[i].x, pb[i].y), cvt2h(pb[i].z, pb[i].w));
        } else {
            char* Blo = Bhi + B_TILE;
            #pragma unroll
            for (int i = 0; i < 8; i++) {
                uint32_t h0, l0, h1, l1;
                split2h(pb[i].x, pb[i].y, h0, l0);
                split2h(pb[i].z, pb[i].w, h1, l1);
                *(uint2*)(Bhi + sBoff[i]) = make_uint2(h0, h1);
                *(uint2*)(Blo + sBoff[i]) = make_uint2(l0, l1);
            }
        }
    };

    preloadB(0);
    stageA(0, 0);
    storeB(0);
    __syncthreads();

    for (int kt = 0; kt < KT; kt++) {
        const int buf = kt & 1;
        const bool more = (kt + 1 < KT);
        if (more) preloadB(kt + 1);       // B LDGs overlap the MMA section

        const uint32_t baseA  = su + buf * BUF;
        const uint32_t baseAl = baseA + A_TILE;
        const uint32_t baseB  = baseA + 2 * A_TILE;
        const uint32_t baseBl = baseB + B_TILE;

        #pragma unroll
        for (int ks = 0; ks < 4; ks++) {
            uint32_t ah[2][4], al[2][4], bh[4][4], bl[4][4];
            #pragma unroll
            for (int c = 0; c < 2; c++) {
                uint32_t o = sw128(aB[c] + ks * 32);
                ldm4(ah[c], baseA  + o);
                ldm4(al[c], baseAl + o);
            }
            #pragma unroll
            for (int j = 0; j < 4; j++) {
                uint32_t o = sw128(bB[j] + ks * 32);
                ldm4(bh[j], baseB + o);
                if (MODE == 1) ldm4(bl[j], baseBl + o);
            }
            // pass 1: Ah * Bh
            #pragma unroll
            for (int j = 0; j < 4; j++)
                #pragma unroll
                for (int c = 0; c < 2; c++) {
                    mma_f16(acc[c][2 * j],     ah[c], bh[j][0], bh[j][2]);
                    mma_f16(acc[c][2 * j + 1], ah[c], bh[j][1], bh[j][3]);
                }
            // pass 2: Al * Bh
            #pragma unroll
            for (int j = 0; j < 4; j++)
                #pragma unroll
                for (int c = 0; c < 2; c++) {
                    mma_f16(acc[c][2 * j],     al[c], bh[j][0], bh[j][2]);
                    mma_f16(acc[c][2 * j + 1], al[c], bh[j][1], bh[j][3]);
                }
            // pass 3 (MODE 1 only): Ah * Bl
            if (MODE == 1) {
                #pragma unroll
                for (int j = 0; j < 4; j++)
                    #pragma unroll
                    for (int c = 0; c < 2; c++) {
                        mma_f16(acc[c][2 * j],     ah[c], bl[j][0], bl[j][2]);
                        mma_f16(acc[c][2 * j + 1], ah[c], bl[j][1], bl[j][3]);
                    }
            }
        }
        if (more) {
            stageA(kt + 1, buf ^ 1);
            storeB(buf ^ 1);
        }
        __syncthreads();
    }

    // ---------------- epilogue ----------------
    const int mw = m0 + wid * 32;
    #pragma unroll
    for (int c = 0; c < 2; c++) {
        #pragma unroll
        for (int half = 0; half < 2; half++) {
            const int r = mw + c * 16 + (lane >> 2) + half * 8;
            if (r >= cnt) continue;
            float s = 0.0f; float* cp;
            if (MODE == 0) {
                cp = g_H + (size_t)(off + r) * FFDIM + n0;
            } else {
                const int tok = g_perm[off + r];
                s = g_w[tok];
                cp = Cg + (size_t)tok * DD + n0;
            }
            #pragma unroll
            for (int j = 0; j < 8; j++) {
                float v0 = acc[c][j][half * 2];
                float v1 = acc[c][j][half * 2 + 1];
                if (MODE == 0) { v0 = gelu_exact(v0); v1 = gelu_exact(v1); }
                else           { v0 *= s; v1 *= s; }
                *(float2*)(cp + j * 8 + (lane & 3) * 2) = make_float2(v0, v1);
            }
        }
    }
}

constexpr int SMEM0 = 2 * (2 * A_TILE + 1 * B_TILE);   // 80 KB
constexpr int SMEM1 = 2 * (2 * A_TILE + 2 * B_TILE);   // 96 KB

// ---------------- launch ----------------
extern "C" void kernel_launch(void* const* d_in, const int* in_sizes, int n_in,
                              void* d_out, int out_size) {
    const float* x  = (const float*)d_in[0];
    const float* Wr = (const float*)d_in[1];
    const float* W1 = (const float*)d_in[2];
    const float* W2 = (const float*)d_in[3];
    float* out = (float*)d_out;

    cudaFuncSetAttribute(moe_gemm_mma<0>, cudaFuncAttributeMaxDynamicSharedMemorySize, SMEM0);
    cudaFuncSetAttribute(moe_gemm_mma<1>, cudaFuncAttributeMaxDynamicSharedMemorySize, SMEM1);

    zero_counts_kernel<<<1, 32>>>();
    router_kernel<<<TT, 256>>>(x, Wr);
    scan_kernel<<<1, 1>>>();
    scatter_kernel<<<TT / 256, 256>>>();

    dim3 g1(MTILES, FFDIM / BN, EE);
    moe_gemm_mma<0><<<g1, 128, SMEM0>>>(x, W1, nullptr);

    dim3 g2(MTILES, DD / BN, EE);
    moe_gemm_mma<1><<<g2, 128, SMEM1>>>(nullptr, W2, out);
}

// round 13
// speedup vs baseline: 5.9527x; 1.1548x over previous
#include <cuda_runtime.h>
#include <math.h>
#include <stdint.h>

#define TT 4096
#define DD 2048
#define FFDIM 8192
#define EE 8
#define MTILES 16   // covers up to 2048 tokens/expert (mean 512)

// ---------------- device scratch ----------------
__device__ uint16_t g_Hh[(size_t)TT * FFDIM];   // H as fp16, sorted rows
__device__ int   g_idx[TT];
__device__ float g_w[TT];
__device__ int   g_counts[EE];
__device__ int   g_offsets[EE];
__device__ int   g_rank[TT];
__device__ int   g_perm[TT];

// ---------------- helpers ----------------
__device__ __forceinline__ uint32_t smem_u32(const void* p) {
    uint32_t a;
    asm("{ .reg .u64 t; cvta.to.shared.u64 t, %1; cvt.u32.u64 %0, t; }" : "=r"(a) : "l"(p));
    return a;
}
__device__ __forceinline__ uint32_t sw128(uint32_t b) { return b ^ ((b >> 3) & 0x70); }

__device__ __forceinline__ uint32_t cvt2h(float f0, float f1) {
    uint32_t h;
    asm("cvt.rn.f16x2.f32 %0, %1, %2;" : "=r"(h) : "f"(f1), "f"(f0));
    return h;
}

__device__ __forceinline__ void ldm4(uint32_t* r, uint32_t addr) {
    asm volatile("ldmatrix.sync.aligned.m8n8.x4.shared.b16 {%0,%1,%2,%3}, [%4];"
        : "=r"(r[0]), "=r"(r[1]), "=r"(r[2]), "=r"(r[3]) : "r"(addr));
}

__device__ __forceinline__ void mma_f16(float* d, const uint32_t* a, uint32_t b0, uint32_t b1) {
    asm volatile("mma.sync.aligned.m16n8k16.row.col.f32.f16.f16.f32 "
        "{%0,%1,%2,%3}, {%4,%5,%6,%7}, {%8,%9}, {%0,%1,%2,%3};"
        : "+f"(d[0]), "+f"(d[1]), "+f"(d[2]), "+f"(d[3])
        : "r"(a[0]), "r"(a[1]), "r"(a[2]), "r"(a[3]), "r"(b0), "r"(b1));
}

__device__ __forceinline__ float gelu_exact(float v) {
    return 0.5f * v * (1.0f + erff(v * 0.70710678118654752440f));
}

// ---------------- router pipeline ----------------
__global__ void zero_counts_kernel() { if (threadIdx.x < EE) g_counts[threadIdx.x] = 0; }

__global__ void router_kernel(const float* __restrict__ x, const float* __restrict__ Wr) {
    const int t = blockIdx.x;
    const int warp = threadIdx.x >> 5, lane = threadIdx.x & 31;
    const float* xr = x + (size_t)t * DD;
    const float* wr = Wr + (size_t)warp * DD;
    float acc = 0.0f;
    for (int d = lane * 4; d < DD; d += 128) {
        float4 xv = *(const float4*)(xr + d);
        float4 wv = *(const float4*)(wr + d);
        acc += xv.x * wv.x + xv.y * wv.y + xv.z * wv.z + xv.w * wv.w;
    }
    #pragma unroll
    for (int o = 16; o; o >>= 1) acc += __shfl_xor_sync(0xFFFFFFFFu, acc, o);
    __shared__ float slog[EE];
    if (lane == 0) slog[warp] = acc;
    __syncthreads();
    if (threadIdx.x == 0) {
        float mx = slog[0]; int mi = 0;
        #pragma unroll
        for (int e = 1; e < EE; e++) if (slog[e] > mx) { mx = slog[e]; mi = e; }
        float s = 0.0f;
        #pragma unroll
        for (int e = 0; e < EE; e++) s += expf(slog[e] - mx);
        g_idx[t] = mi;
        g_w[t] = 1.0f / s;
        g_rank[t] = atomicAdd(&g_counts[mi], 1);
    }
}

__global__ void scan_kernel() {
    int s = 0;
    #pragma unroll
    for (int e = 0; e < EE; e++) { g_offsets[e] = s; s += g_counts[e]; }
}

__global__ void scatter_kernel() {
    int t = blockIdx.x * blockDim.x + threadIdx.x;
    if (t < TT) g_perm[g_offsets[g_idx[t]] + g_rank[t]] = t;
}

// ---------------- mma.sync grouped GEMM (single-pass fp16) ----------------
// MODE 0: Hh = fp16( gelu( x @ W1 ) )    A=x->fp16, B=W1->fp16
// MODE 1: out = ( Hh @ W2 ) * w          A=Hh direct, B=W2->fp16
constexpr int BM = 128, BN = 64, BKS = 64;
constexpr int A_TILE = BM * BKS * 2;             // 16 KB
constexpr int B_TILE = BN * BKS * 2;             // 8 KB
constexpr int BUF = A_TILE + B_TILE;             // 24 KB
constexpr int SMEMT = 2 * BUF;                   // 48 KB double-buffered

template<int MODE>
__global__ __launch_bounds__(128, 3) void moe_gemm_mma(
    const float* __restrict__ Ag, const float* __restrict__ Bg, float* __restrict__ Cg)
{
    constexpr int K  = (MODE == 0) ? DD : FFDIM;
    constexpr int NN = (MODE == 0) ? FFDIM : DD;
    constexpr int KT = K / BKS;

    const int e   = blockIdx.z;
    const int cnt = g_counts[e];
    const int m0  = blockIdx.x * BM;             // m fastest -> B tile L2 reuse
    if (m0 >= cnt) return;
    const int off = g_offsets[e];
    const int n0  = blockIdx.y * BN;

    extern __shared__ __align__(1024) char smem[];
    const uint32_t su = smem_u32(smem);
    const int tid = threadIdx.x, wid = tid >> 5, lane = tid & 31;

    // ---- staging geometry ----
    // A: thread owns 16 (m, k4) units: m = (tid>>4) + 8*i, k4 = tid&15 (4 k-elems each)
    const char* aBase = (MODE == 0) ? (const char*)Ag : (const char*)g_Hh;
    uint32_t aOff[16], sAoff[16];
    {
        const int mB = tid >> 4, k4 = tid & 15;
        #pragma unroll
        for (int i = 0; i < 16; i++) {
            int m = mB + 8 * i;
            int r = m0 + m;
            bool v = r < cnt;
            uint32_t rowBytes;
            if (MODE == 0) {
                int tok = v ? g_perm[off + r] : g_perm[off];
                rowBytes = (uint32_t)tok * (DD * 4u) + k4 * 16u;
            } else {
                rowBytes = (uint32_t)(off + (v ? r : 0)) * (FFDIM * 2u) + k4 * 8u;
            }
            aOff[i]  = rowBytes;
            sAoff[i] = sw128((uint32_t)(m * 128 + k4 * 8));
        }
    }
    // B: thread owns n-row rB = tid&63, 8 k-groups with stagger
    const int rB = tid & 63;
    const float* bCol = Bg + (size_t)e * ((size_t)K * NN) + (size_t)(n0 + rB);
    int kkB[8]; uint32_t sBoff[8];
    {
        const int gB = tid >> 6, stag = (rB >> 3) & 3;
        #pragma unroll
        for (int i = 0; i < 8; i++) {
            int g = ((gB + 2 * i) + stag) & 15;
            kkB[i]   = g * 4;
            sBoff[i] = sw128((uint32_t)(rB * 128 + g * 8));
        }
    }

    // ---- ldmatrix geometry: 4 warps, warp wid owns rows [wid*32, wid*32+32), all 64 n ----
    uint32_t aB[2], bB[4];
    #pragma unroll
    for (int c = 0; c < 2; c++) {
        int row = wid * 32 + c * 16 + (lane & 15);
        aB[c] = (uint32_t)(row * 128 + (lane >> 4) * 16);
    }
    #pragma unroll
    for (int j = 0; j < 4; j++) {
        int row = j * 16 + (lane & 15);
        bB[j] = (uint32_t)(row * 128 + (lane >> 4) * 16);
    }

    float acc[2][8][4];
    #pragma unroll
    for (int c = 0; c < 2; c++)
        #pragma unroll
        for (int j = 0; j < 8; j++)
            #pragma unroll
            for (int q = 0; q < 4; q++) acc[c][j][q] = 0.0f;

    float4 pb[8];
    auto preloadB = [&](int kt) {
        const int k0 = kt * BKS;
        #pragma unroll
        for (int i = 0; i < 8; i++) {
            const float* p = bCol + (size_t)(k0 + kkB[i]) * NN;
            pb[i] = make_float4(p[0], p[(size_t)NN], p[(size_t)2 * NN], p[(size_t)3 * NN]);
        }
    };

    auto stageA = [&](int kt, int b) {
        char* Ah = smem + b * BUF;
        if (MODE == 0) {
            const uint32_t kByte = (uint32_t)(kt * BKS * 4);
            #pragma unroll
            for (int i = 0; i < 16; i++) {
                float4 v = *(const float4*)(aBase + aOff[i] + kByte);
                *(uint2*)(Ah + sAoff[i]) = make_uint2(cvt2h(v.x, v.y), cvt2h(v.z, v.w));
            }
        } else {
            const uint32_t kByte = (uint32_t)(kt * BKS * 2);
            #pragma unroll
            for (int i = 0; i < 16; i++)
                *(uint2*)(Ah + sAoff[i]) = *(const uint2*)(aBase + aOff[i] + kByte);
        }
    };
    auto storeB = [&](int b) {
        char* Bh = smem + b * BUF + A_TILE;
        #pragma unroll
        for (int i = 0; i < 8; i++)
            *(uint2*)(Bh + sBoff[i]) = make_uint2(cvt2h(pb[i].x, pb[i].y), cvt2h(pb[i].z, pb[i].w));
    };

    preloadB(0);
    stageA(0, 0);
    storeB(0);
    __syncthreads();

    for (int kt = 0; kt < KT; kt++) {
        const int buf = kt & 1;
        const bool more = (kt + 1 < KT);
        if (more) preloadB(kt + 1);       // B LDGs overlap the MMA section

        const uint32_t baseA = su + buf * BUF;
        const uint32_t baseB = baseA + A_TILE;

        #pragma unroll
        for (int ks = 0; ks < 4; ks++) {
            uint32_t ah[2][4], bh[4][4];
            #pragma unroll
            for (int c = 0; c < 2; c++) {
                uint32_t o = sw128(aB[c] + ks * 32);
                ldm4(ah[c], baseA + o);
            }
            #pragma unroll
            for (int j = 0; j < 4; j++) {
                uint32_t o = sw128(bB[j] + ks * 32);
                ldm4(bh[j], baseB + o);
            }
            #pragma unroll
            for (int j = 0; j < 4; j++)
                #pragma unroll
                for (int c = 0; c < 2; c++) {
                    mma_f16(acc[c][2 * j],     ah[c], bh[j][0], bh[j][2]);
                    mma_f16(acc[c][2 * j + 1], ah[c], bh[j][1], bh[j][3]);
                }
        }
        if (more) {
            stageA(kt + 1, buf ^ 1);
            storeB(buf ^ 1);
        }
        __syncthreads();
    }

    // ---------------- epilogue ----------------
    const int mw = m0 + wid * 32;
    #pragma unroll
    for (int c = 0; c < 2; c++) {
        #pragma unroll
        for (int half = 0; half < 2; half++) {
            const int r = mw + c * 16 + (lane >> 2) + half * 8;
            if (r >= cnt) continue;
            if (MODE == 0) {
                uint16_t* hp = g_Hh + (size_t)(off + r) * FFDIM + n0;
                #pragma unroll
                for (int j = 0; j < 8; j++) {
                    float v0 = gelu_exact(acc[c][j][half * 2]);
                    float v1 = gelu_exact(acc[c][j][half * 2 + 1]);
                    *(uint32_t*)(hp + j * 8 + (lane & 3) * 2) = cvt2h(v0, v1);
                }
            } else {
                const int tok = g_perm[off + r];
                const float s = g_w[tok];
                float* cp = Cg + (size_t)tok * DD + n0;
                #pragma unroll
                for (int j = 0; j < 8; j++) {
                    float v0 = acc[c][j][half * 2] * s;
                    float v1 = acc[c][j][half * 2 + 1] * s;
                    *(float2*)(cp + j * 8 + (lane & 3) * 2) = make_float2(v0, v1);
                }
            }
        }
    }
}

// ---------------- launch ----------------
extern "C" void kernel_launch(void* const* d_in, const int* in_sizes, int n_in,
                              void* d_out, int out_size) {
    const float* x  = (const float*)d_in[0];
    const float* Wr = (const float*)d_in[1];
    const float* W1 = (const float*)d_in[2];
    const float* W2 = (const float*)d_in[3];
    float* out = (float*)d_out;

    cudaFuncSetAttribute(moe_gemm_mma<0>, cudaFuncAttributeMaxDynamicSharedMemorySize, SMEMT);
    cudaFuncSetAttribute(moe_gemm_mma<1>, cudaFuncAttributeMaxDynamicSharedMemorySize, SMEMT);

    zero_counts_kernel<<<1, 32>>>();
    router_kernel<<<TT, 256>>>(x, Wr);
    scan_kernel<<<1, 1>>>();
    scatter_kernel<<<TT / 256, 256>>>();

    dim3 g1(MTILES, FFDIM / BN, EE);
    moe_gemm_mma<0><<<g1, 128, SMEMT>>>(x, W1, nullptr);

    dim3 g2(MTILES, DD / BN, EE);
    moe_gemm_mma<1><<<g2, 128, SMEMT>>>(nullptr, W2, out);
}

// round 14
// speedup vs baseline: 12.1461x; 2.0404x over previous
#include <cuda_runtime.h>
#include <math.h>
#include <stdint.h>

#define TT 4096
#define DD 2048
#define FFDIM 8192
#define EE 8
#define MTILES 16   // covers up to 2048 tokens/expert (mean 512)

// ---------------- device scratch (static, no allocations) ----------------
__device__ uint16_t g_xh[(size_t)TT * DD];              // x as fp16 [T][D]
__device__ uint16_t g_Hh[(size_t)TT * FFDIM];           // H as fp16, sorted rows
__device__ uint16_t g_W1h[(size_t)EE * FFDIM * DD];     // [E][N=F][K=D] fp16
__device__ uint16_t g_W2h[(size_t)EE * DD * FFDIM];     // [E][N=D][K=F] fp16
__device__ int   g_idx[TT];
__device__ float g_w[TT];
__device__ int   g_counts[EE];
__device__ int   g_offsets[EE];
__device__ int   g_rank[TT];
__device__ int   g_perm[TT];

// ---------------- helpers ----------------
__device__ __forceinline__ uint32_t smem_u32(const void* p) {
    uint32_t a;
    asm("{ .reg .u64 t; cvta.to.shared.u64 t, %1; cvt.u32.u64 %0, t; }" : "=r"(a) : "l"(p));
    return a;
}
__device__ __forceinline__ uint32_t sw128(uint32_t b) { return b ^ ((b >> 3) & 0x70); }

__device__ __forceinline__ uint32_t cvt2h(float f0, float f1) {
    uint32_t h;
    asm("cvt.rn.f16x2.f32 %0, %1, %2;" : "=r"(h) : "f"(f1), "f"(f0));
    return h;
}

__device__ __forceinline__ void ldm4(uint32_t* r, uint32_t addr) {
    asm volatile("ldmatrix.sync.aligned.m8n8.x4.shared.b16 {%0,%1,%2,%3}, [%4];"
        : "=r"(r[0]), "=r"(r[1]), "=r"(r[2]), "=r"(r[3]) : "r"(addr));
}
__device__ __forceinline__ void mma_f16(float* d, const uint32_t* a, uint32_t b0, uint32_t b1) {
    asm volatile("mma.sync.aligned.m16n8k16.row.col.f32.f16.f16.f32 "
        "{%0,%1,%2,%3}, {%4,%5,%6,%7}, {%8,%9}, {%0,%1,%2,%3};"
        : "+f"(d[0]), "+f"(d[1]), "+f"(d[2]), "+f"(d[3])
        : "r"(a[0]), "r"(a[1]), "r"(a[2]), "r"(a[3]), "r"(b0), "r"(b1));
}
#define CP16(dst, src) asm volatile("cp.async.cg.shared.global [%0], [%1], 16;" :: "r"(dst), "l"(src))
#define CP_COMMIT()    asm volatile("cp.async.commit_group;" ::: "memory")
#define CP_WAIT1()     asm volatile("cp.async.wait_group 1;" ::: "memory")
#define CP_WAIT0()     asm volatile("cp.async.wait_group 0;" ::: "memory")

__device__ __forceinline__ float gelu_exact(float v) {
    return 0.5f * v * (1.0f + erff(v * 0.70710678118654752440f));
}

// ---------------- pre-pass conversion ----------------
__global__ void cvt_x_kernel(const float* __restrict__ x) {
    size_t i4 = (size_t)blockIdx.x * 256 + threadIdx.x;   // TT*DD/4 units
    float4 v = ((const float4*)x)[i4];
    ((uint2*)g_xh)[i4] = make_uint2(cvt2h(v.x, v.y), cvt2h(v.z, v.w));
}

// W [E][K][N] fp32 -> [E][N][K] fp16 (transpose + convert), 32x32 tiles
template<int L>
__global__ void cvt_w_kernel(const float* __restrict__ W) {
    constexpr int KK = (L == 0) ? DD : FFDIM;
    constexpr int NN = (L == 0) ? FFDIM : DD;
    __shared__ float t[32][33];
    const int e = blockIdx.z, n0 = blockIdx.x * 32, k0 = blockIdx.y * 32;
    const int nn = threadIdx.x & 31, kr = threadIdx.x >> 5;
    const float* src = W + ((size_t)e * KK + k0) * NN + n0;
    #pragma unroll
    for (int i = 0; i < 4; i++)
        t[kr + 8 * i][nn] = src[(size_t)(kr + 8 * i) * NN + nn];
    __syncthreads();
    const int n = threadIdx.x >> 3, kg = (threadIdx.x & 7) * 4;
    uint16_t* dst = ((L == 0) ? g_W1h : g_W2h) + ((size_t)e * NN + n0 + n) * KK + k0 + kg;
    *(uint2*)dst = make_uint2(cvt2h(t[kg][n], t[kg + 1][n]), cvt2h(t[kg + 2][n], t[kg + 3][n]));
}

// ---------------- router pipeline ----------------
__global__ void zero_counts_kernel() { if (threadIdx.x < EE) g_counts[threadIdx.x] = 0; }

__global__ void router_kernel(const float* __restrict__ x, const float* __restrict__ Wr) {
    const int t = blockIdx.x;
    const int warp = threadIdx.x >> 5, lane = threadIdx.x & 31;
    const float* xr = x + (size_t)t * DD;
    const float* wr = Wr + (size_t)warp * DD;
    float acc = 0.0f;
    for (int d = lane * 4; d < DD; d += 128) {
        float4 xv = *(const float4*)(xr + d);
        float4 wv = *(const float4*)(wr + d);
        acc += xv.x * wv.x + xv.y * wv.y + xv.z * wv.z + xv.w * wv.w;
    }
    #pragma unroll
    for (int o = 16; o; o >>= 1) acc += __shfl_xor_sync(0xFFFFFFFFu, acc, o);
    __shared__ float slog[EE];
    if (lane == 0) slog[warp] = acc;
    __syncthreads();
    if (threadIdx.x == 0) {
        float mx = slog[0]; int mi = 0;
        #pragma unroll
        for (int e = 1; e < EE; e++) if (slog[e] > mx) { mx = slog[e]; mi = e; }
        float s = 0.0f;
        #pragma unroll
        for (int e = 0; e < EE; e++) s += expf(slog[e] - mx);
        g_idx[t] = mi;
        g_w[t] = 1.0f / s;
        g_rank[t] = atomicAdd(&g_counts[mi], 1);
    }
}

__global__ void scan_kernel() {
    int s = 0;
    #pragma unroll
    for (int e = 0; e < EE; e++) { g_offsets[e] = s; s += g_counts[e]; }
}

__global__ void scatter_kernel() {
    int t = blockIdx.x * blockDim.x + threadIdx.x;
    if (t < TT) g_perm[g_offsets[g_idx[t]] + g_rank[t]] = t;
}

// ---------------- fp16 grouped GEMM, cp.async staging, 3-stage ring ----------------
// MODE 0: Hh = fp16( gelu( xh @ W1h^T ) )
// MODE 1: out = ( Hh @ W2h^T ) * w
constexpr int BM = 128, BN = 64, BKS = 64;
constexpr int A_TILE = BM * 128;                 // 16 KB (128B = 64 fp16 per row)
constexpr int B_TILE = BN * 128;                 // 8 KB
constexpr int STAGE  = A_TILE + B_TILE;          // 24 KB
constexpr int SMEMT  = 3 * STAGE;                // 72 KB

template<int MODE>
__global__ __launch_bounds__(128, 3) void moe_gemm_mma(float* __restrict__ Cg)
{
    constexpr int K  = (MODE == 0) ? DD : FFDIM;
    constexpr int NN = (MODE == 0) ? FFDIM : DD;
    constexpr int KT = K / BKS;

    const int e   = blockIdx.z;
    const int cnt = g_counts[e];
    const int m0  = blockIdx.x * BM;             // m fastest -> B tile L2 reuse
    if (m0 >= cnt) return;
    const int off = g_offsets[e];
    const int n0  = blockIdx.y * BN;

    extern __shared__ __align__(1024) char smem[];
    const uint32_t su = smem_u32(smem);
    const int tid = threadIdx.x, wid = tid >> 5, lane = tid & 31;

    const char* Abase = (MODE == 0) ? (const char*)g_xh : (const char*)g_Hh;
    const char* Bbase = (MODE == 0) ? (const char*)g_W1h : (const char*)g_W2h;

    // ---- cp.async staging geometry: kc = tid&7 (16B chunk in 128B row) ----
    const int kc = tid & 7;
    uint32_t aByte[8], sA[8];
    #pragma unroll
    for (int i = 0; i < 8; i++) {
        int m = (tid >> 3) + 16 * i;
        int r = m0 + m;
        bool v = r < cnt;
        uint32_t row;
        if (MODE == 0) row = (uint32_t)(v ? g_perm[off + r] : g_perm[off]);
        else           row = (uint32_t)(off + (v ? r : 0));
        aByte[i] = row * (uint32_t)(K * 2) + kc * 16u;
        sA[i] = sw128((uint32_t)(m * 128 + kc * 16));
    }
    size_t bByte[4]; uint32_t sB[4];
    #pragma unroll
    for (int i = 0; i < 4; i++) {
        int rb = (tid >> 3) + 16 * i;
        bByte[i] = ((size_t)e * NN + n0 + rb) * (size_t)(K * 2) + kc * 16u;
        sB[i] = sw128((uint32_t)(rb * 128 + kc * 16));
    }

    // ---- ldmatrix geometry (proven R13) ----
    uint32_t aB[2], bB[4];
    #pragma unroll
    for (int c = 0; c < 2; c++) {
        int row = wid * 32 + c * 16 + (lane & 15);
        aB[c] = (uint32_t)(row * 128 + (lane >> 4) * 16);
    }
    #pragma unroll
    for (int j = 0; j < 4; j++) {
        int row = j * 16 + (lane & 15);
        bB[j] = (uint32_t)(row * 128 + (lane >> 4) * 16);
    }

    float acc[2][8][4];
    #pragma unroll
    for (int c = 0; c < 2; c++)
        #pragma unroll
        for (int j = 0; j < 8; j++)
            #pragma unroll
            for (int q = 0; q < 4; q++) acc[c][j][q] = 0.0f;

    auto stage = [&](int kt, int b) {
        const uint32_t d = su + b * STAGE;
        const uint32_t ko = (uint32_t)(kt * 128);   // 64 fp16 = 128 bytes
        #pragma unroll
        for (int i = 0; i < 8; i++) CP16(d + sA[i], Abase + aByte[i] + ko);
        #pragma unroll
        for (int i = 0; i < 4; i++) CP16(d + A_TILE + sB[i], Bbase + bByte[i] + ko);
    };

    stage(0, 0); CP_COMMIT();
    stage(1, 1); CP_COMMIT();

    for (int kt = 0; kt < KT; kt++) {
        const int b = kt % 3;
        if (kt + 2 < KT) CP_WAIT1(); else CP_WAIT0();
        __syncthreads();
        if (kt + 2 < KT) { stage(kt + 2, (kt + 2) % 3); CP_COMMIT(); }

        const uint32_t baseA = su + b * STAGE;
        const uint32_t baseB = baseA + A_TILE;
        #pragma unroll
        for (int ks = 0; ks < 4; ks++) {
            uint32_t ah[2][4], bh[4][4];
            #pragma unroll
            for (int c = 0; c < 2; c++) {
                uint32_t o = sw128(aB[c] + ks * 32);
                ldm4(ah[c], baseA + o);
            }
            #pragma unroll
            for (int j = 0; j < 4; j++) {
                uint32_t o = sw128(bB[j] + ks * 32);
                ldm4(bh[j], baseB + o);
            }
            #pragma unroll
            for (int j = 0; j < 4; j++)
                #pragma unroll
                for (int c = 0; c < 2; c++) {
                    mma_f16(acc[c][2 * j],     ah[c], bh[j][0], bh[j][2]);
                    mma_f16(acc[c][2 * j + 1], ah[c], bh[j][1], bh[j][3]);
                }
        }
        __syncthreads();
    }

    // ---------------- epilogue ----------------
    const int mw = m0 + wid * 32;
    #pragma unroll
    for (int c = 0; c < 2; c++) {
        #pragma unroll
        for (int half = 0; half < 2; half++) {
            const int r = mw + c * 16 + (lane >> 2) + half * 8;
            if (r >= cnt) continue;
            if (MODE == 0) {
                uint16_t* hp = g_Hh + (size_t)(off + r) * FFDIM + n0;
                #pragma unroll
                for (int j = 0; j < 8; j++) {
                    float v0 = gelu_exact(acc[c][j][half * 2]);
                    float v1 = gelu_exact(acc[c][j][half * 2 + 1]);
                    *(uint32_t*)(hp + j * 8 + (lane & 3) * 2) = cvt2h(v0, v1);
                }
            } else {
                const int tok = g_perm[off + r];
                const float s = g_w[tok];
                float* cp = Cg + (size_t)tok * DD + n0;
                #pragma unroll
                for (int j = 0; j < 8; j++) {
                    float v0 = acc[c][j][half * 2] * s;
                    float v1 = acc[c][j][half * 2 + 1] * s;
                    *(float2*)(cp + j * 8 + (lane & 3) * 2) = make_float2(v0, v1);
                }
            }
        }
    }
}

// ---------------- launch ----------------
extern "C" void kernel_launch(void* const* d_in, const int* in_sizes, int n_in,
                              void* d_out, int out_size) {
    const float* x  = (const float*)d_in[0];
    const float* Wr = (const float*)d_in[1];
    const float* W1 = (const float*)d_in[2];
    const float* W2 = (const float*)d_in[3];
    float* out = (float*)d_out;

    cudaFuncSetAttribute(moe_gemm_mma<0>, cudaFuncAttributeMaxDynamicSharedMemorySize, SMEMT);
    cudaFuncSetAttribute(moe_gemm_mma<1>, cudaFuncAttributeMaxDynamicSharedMemorySize, SMEMT);

    cvt_x_kernel<<<TT * DD / 1024, 256>>>(x);
    cvt_w_kernel<0><<<dim3(FFDIM / 32, DD / 32, EE), 256>>>(W1);
    cvt_w_kernel<1><<<dim3(DD / 32, FFDIM / 32, EE), 256>>>(W2);

    zero_counts_kernel<<<1, 32>>>();
    router_kernel<<<TT, 256>>>(x, Wr);
    scan_kernel<<<1, 1>>>();
    scatter_kernel<<<TT / 256, 256>>>();

    dim3 g1(MTILES, FFDIM / BN, EE);
    moe_gemm_mma<0><<<g1, 128, SMEMT>>>(nullptr);

    dim3 g2(MTILES, DD / BN, EE);
    moe_gemm_mma<1><<<g2, 128, SMEMT>>>(out);
}